// round 11
// baseline (speedup 1.0000x reference)
#include <cuda_runtime.h>
#include <cuda_fp16.h>
#include <math.h>

#define BB 16384
#define SS 16
#define NSTEPS 50
#define LATENT 128
#define HID 64
#define DTC 0.02f
#define SQRT_DT 0.14142135623730951f
#define LOG2E 1.4426950408889634f
#define LN2 0.6931471805599453f
#define EXPM50 1.9287498479639178e-22f /* exp(-50) */

// Scratch (no cudaMalloc allowed)
__device__ unsigned g_zch[BB * 32]; // per-b hidden bias, f16x2-packed pairs (32 pairs = 64 units)
__device__ float g_halfb[BB];       // 0.5*boundary
__device__ float g_ndt[BB];         // non-decision time

__device__ __forceinline__ float ex2f(float v) {
    float r; asm("ex2.approx.f32 %0, %1;" : "=f"(r) : "f"(v)); return r;
}
__device__ __forceinline__ float lg2f(float v) {
    float r; asm("lg2.approx.f32 %0, %1;" : "=f"(r) : "f"(v)); return r;
}
__device__ __forceinline__ float tanhapx(float v) {
    float r; asm("tanh.approx.f32 %0, %1;" : "=f"(r) : "f"(v)); return r;
}
__device__ __forceinline__ half2 tanh2h(half2 x) {
    unsigned xi = *reinterpret_cast<unsigned*>(&x);
    unsigned r;
    asm("tanh.approx.f16x2 %0, %1;" : "=r"(r) : "r"(xi));
    return *reinterpret_cast<half2*>(&r);
}
__device__ __forceinline__ half2 u2h(unsigned v) {
    return *reinterpret_cast<half2*>(&v);
}
__device__ __forceinline__ unsigned h2u(half2 v) {
    return *reinterpret_cast<unsigned*>(&v);
}
// Sum the two f16 halves of v as f32, using ALU-pipe bit-expansion
// (exact for normal f16; subnormals introduce <= 6.1e-5 abs error).
__device__ __forceinline__ float h2sum(half2 v) {
    unsigned r = *reinterpret_cast<unsigned*>(&v);
    unsigned lo = ((r << 16) & 0x80000000u) | (((r & 0x7FFFu) << 13) + 0x38000000u);
    unsigned hi = (r & 0x80000000u) | (((r >> 3) & 0x0FFFE000u) + 0x38000000u);
    return __uint_as_float(lo) + __uint_as_float(hi);
}
__device__ __forceinline__ float fix_out(float v) {
    if (isnan(v)) return 0.0f;
    return fminf(fmaxf(v, -3.402823466e38f), 3.402823466e38f);
}

// ---------------------------------------------------------------------------
// Precompute: zc[b][j] = b1[j] + sum_k z[b,k]*W1[j,2+k], stored f16x2-packed;
// boundary & ndt per b.
// ---------------------------------------------------------------------------
__global__ __launch_bounds__(256) void precompute_kernel(
    const float* __restrict__ z,  const float* __restrict__ W1,
    const float* __restrict__ b1, const float* __restrict__ Wb,
    const float* __restrict__ bbv, const float* __restrict__ Wn,
    const float* __restrict__ bnv)
{
    __shared__ __align__(16) float sW[HID * 130];   // whole W1, 33.3KB
    __shared__ __align__(16) float sz[16 * LATENT]; // 16 z rows, 8KB
    const int tid = threadIdx.x;
    const int b0 = blockIdx.x * 16;

    for (int i = tid; i < HID * 130; i += 256) sW[i] = W1[i];
    for (int i = tid; i < 16 * LATENT; i += 256) sz[i] = z[b0 * LATENT + i];
    __syncthreads();

    const int j = tid & 63;
    const int bg = tid >> 6;   // 0..3, each handles 4 b's
    const float* wrow = sW + j * 130 + 2;
    float a0, a1, a2, a3;
    a0 = a1 = a2 = a3 = b1[j];
    const float* z0 = sz + (bg * 4 + 0) * LATENT;
    const float* z1 = sz + (bg * 4 + 1) * LATENT;
    const float* z2 = sz + (bg * 4 + 2) * LATENT;
    const float* z3 = sz + (bg * 4 + 3) * LATENT;
    #pragma unroll 8
    for (int k = 0; k < LATENT; k += 4) {
        float w0 = wrow[k], w1 = wrow[k + 1], w2 = wrow[k + 2], w3 = wrow[k + 3];
        float4 q0 = *(const float4*)(z0 + k);
        float4 q1 = *(const float4*)(z1 + k);
        float4 q2 = *(const float4*)(z2 + k);
        float4 q3 = *(const float4*)(z3 + k);
        a0 = fmaf(w0, q0.x, a0); a0 = fmaf(w1, q0.y, a0); a0 = fmaf(w2, q0.z, a0); a0 = fmaf(w3, q0.w, a0);
        a1 = fmaf(w0, q1.x, a1); a1 = fmaf(w1, q1.y, a1); a1 = fmaf(w2, q1.z, a1); a1 = fmaf(w3, q1.w, a1);
        a2 = fmaf(w0, q2.x, a2); a2 = fmaf(w1, q2.y, a2); a2 = fmaf(w2, q2.z, a2); a2 = fmaf(w3, q2.w, a2);
        a3 = fmaf(w0, q3.x, a3); a3 = fmaf(w1, q3.y, a3); a3 = fmaf(w2, q3.z, a3); a3 = fmaf(w3, q3.w, a3);
    }

    // pack (j, j+1) pairs into f16x2 via partner shuffle; even j stores
    const float p0 = __shfl_xor_sync(0xffffffffu, a0, 1);
    const float p1 = __shfl_xor_sync(0xffffffffu, a1, 1);
    const float p2 = __shfl_xor_sync(0xffffffffu, a2, 1);
    const float p3 = __shfl_xor_sync(0xffffffffu, a3, 1);
    if ((j & 1) == 0) {
        const int col = j >> 1;   // 0..31
        half2 h0 = __floats2half2_rn(a0, p0);
        half2 h1 = __floats2half2_rn(a1, p1);
        half2 h2v = __floats2half2_rn(a2, p2);
        half2 h3 = __floats2half2_rn(a3, p3);
        g_zch[(b0 + bg * 4 + 0) * 32 + col] = h2u(h0);
        g_zch[(b0 + bg * 4 + 1) * 32 + col] = h2u(h1);
        g_zch[(b0 + bg * 4 + 2) * 32 + col] = h2u(h2v);
        g_zch[(b0 + bg * 4 + 3) * 32 + col] = h2u(h3);
    }

    if (tid < 32) {
        const int bl = tid >> 1;
        const int isn = tid & 1;
        const float* wv = isn ? Wn : Wb;
        const float* zz = sz + bl * LATENT;
        float acc = isn ? bnv[0] : bbv[0];
        #pragma unroll 8
        for (int k = 0; k < LATENT; k++) acc = fmaf(wv[k], zz[k], acc);
        float sp = fmaxf(acc, 0.0f) + log1pf(expf(-fabsf(acc)));
        if (isn) g_ndt[b0 + bl] = sp + 0.05f;
        else     g_halfb[b0 + bl] = 0.5f * (sp + 0.3f);
    }
}

// ---------------------------------------------------------------------------
// Main SDE kernel. ONE THREAD = ONE FULL SIM (all 64 hidden units = 32 f16x2
// pairs). Uniform weights {w1x, w1t, w2a, w2b} packed per-pair as one uint4
// in SMEM — one broadcast LDS.128 per pair per step (conflict-free, ~0 BW).
// Per-b zc pairs live in registers (32 regs). Layer 1 entirely f16
// (HFMA2 + tanh.approx.f16x2); SDE state & tail in f32. No shuffles/smem in
// the step loop. Block 256 = 16 b's x 16 sims.
// ---------------------------------------------------------------------------
__global__ __launch_bounds__(256, 3) void sde_kernel(
    const float* __restrict__ W1, const float* __restrict__ W2,
    const float* __restrict__ b2, const float* __restrict__ noise,
    const float* __restrict__ osc, const float* __restrict__ obi,
    float* __restrict__ out)
{
    __shared__ __align__(16) uint4 sWp[32];   // {w1x2, w1t2, w2a2, w2b2} per pair

    const int tid = threadIdx.x;
    const int s   = tid & 15;         // sim
    const int b   = blockIdx.x * 16 + (tid >> 4);

    if (tid < 32) {
        const int j = tid * 2;
        half2 wx = __floats2half2_rn(W1[j * 130],     W1[(j + 1) * 130]);
        half2 wt = __floats2half2_rn(W1[j * 130 + 1], W1[(j + 1) * 130 + 1]);
        half2 wa = __floats2half2_rn(W2[j],       W2[j + 1]);
        half2 wb = __floats2half2_rn(W2[HID + j], W2[HID + j + 1]);
        sWp[tid] = make_uint4(h2u(wx), h2u(wt), h2u(wa), h2u(wb));
    }

    // per-b hidden bias pairs in registers
    half2 zc2[32];
    #pragma unroll
    for (int p = 0; p < 32; p++) zc2[p] = u2h(g_zch[b * 32 + p]);

    const float b2x = b2[0], b2y = b2[1];
    const float half_b = g_halfb[b];
    const half2 hzero = __floats2half2_rn(0.0f, 0.0f);
    __syncthreads();

    float x = 0.0f, p_surv = 1.0f, exp_rt = 0.0f, exp_corr = 0.0f;
    const int nidx = b * SS + s;
    float nz = noise[nidx];

    #pragma unroll 1
    for (int k = 0; k < NSTEPS; k++) {
        const int k1 = (k + 1 < NSTEPS) ? (k + 1) : (NSTEPS - 1);
        const float nz_next = noise[k1 * (BB * SS) + nidx];  // prefetch
        const float tk = (float)k * DTC;
        const half2 tkh = __float2half2_rn(tk);
        const half2 xh  = __float2half2_rn(x);

        half2 da0 = hzero, db0 = hzero, da1 = hzero, db1 = hzero;
        #pragma unroll
        for (int p = 0; p < 32; p += 2) {
            const uint4 wv0 = sWp[p];
            const uint4 wv1 = sWp[p + 1];
            const half2 base0 = __hfma2(tkh, u2h(wv0.y), zc2[p]);
            const half2 base1 = __hfma2(tkh, u2h(wv1.y), zc2[p + 1]);
            const half2 u0 = __hfma2(xh, u2h(wv0.x), base0);
            const half2 u1 = __hfma2(xh, u2h(wv1.x), base1);
            const half2 h0 = tanh2h(u0);
            const half2 h1 = tanh2h(u1);
            da0 = __hfma2(h0, u2h(wv0.z), da0);
            db0 = __hfma2(h0, u2h(wv0.w), db0);
            da1 = __hfma2(h1, u2h(wv1.z), da1);
            db1 = __hfma2(h1, u2h(wv1.w), db1);
        }
        const float pd = h2sum(da0) + h2sum(da1);
        const float pf = h2sum(db0) + h2sum(db1);

        const float dyn0 = pd + b2x;
        const float dyn1 = pf + b2y;
        const float drift = fminf(fmaxf(dyn0, -5.0f), 5.0f);
        // softplus(dyn1) = max(v,0) + ln(1 + e^{-|v|})
        const float e1 = ex2f(-fabsf(dyn1) * LOG2E);
        const float sp = fmaxf(dyn1, 0.0f) + lg2f(1.0f + e1) * LN2;
        const float diff = sp + 0.1f;

        x = fmaf(diff * SQRT_DT, nz, fmaf(drift, DTC, x));
        x = fminf(fmaxf(x, -10.0f), 10.0f);

        const float dist = fabsf(x) - half_b;
        // sigmoid(20*dist) = 0.5 + 0.5*tanh(10*dist)
        const float sg = fmaf(0.5f, tanhapx(10.0f * dist), 0.5f);
        const float hz = fminf(fmaxf(sg, 0.0f), 0.99f);
        const float sb = fmaxf(p_surv, EXPM50);
        const float cp = sb * hz;
        p_surv = p_surv * (1.0f - hz);
        exp_rt = fmaf(cp, tk + DTC, exp_rt);
        exp_corr += (x > 0.0f) ? cp : 0.0f;

        nz = nz_next;
    }

    const float rem = fmaxf(p_surv, EXPM50);
    exp_rt  = fmaf(rem, (float)NSTEPS * DTC, exp_rt);
    exp_corr = fmaf(rem, 0.5f, exp_corr);
    const float rtms = (exp_rt + g_ndt[b]) * 1000.0f;

    // butterfly reductions within the 16-lane b-group
    float srt = rtms;
    float scr = exp_corr;
    #pragma unroll
    for (int off = 1; off < 16; off <<= 1) {
        srt += __shfl_xor_sync(0xffffffffu, srt, off);
        scr += __shfl_xor_sync(0xffffffffu, scr, off);
    }
    const float m = srt * (1.0f / 16.0f);
    const float c = scr * (1.0f / 16.0f);
    const float d = rtms - m;
    float v = d * d;
    #pragma unroll
    for (int off = 1; off < 16; off <<= 1) {
        v += __shfl_xor_sync(0xffffffffu, v, off);
    }

    if (s == 0) {
        const float sd = sqrtf(v * (1.0f / 15.0f));  // ddof=1
        const float o0 = m * osc[0] + obi[0];
        const float o1 = (sd + 0.001f) * osc[1] + obi[1];
        const float o2 = c * osc[2] + obi[2];
        out[b * 3 + 0] = fix_out(o0);
        out[b * 3 + 1] = fix_out(o1);
        out[b * 3 + 2] = fix_out(o2);
    }
}

extern "C" void kernel_launch(void* const* d_in, const int* in_sizes, int n_in,
                              void* d_out, int out_size)
{
    const float* z   = (const float*)d_in[0];
    const float* W1  = (const float*)d_in[1];
    const float* b1  = (const float*)d_in[2];
    const float* W2  = (const float*)d_in[3];
    const float* b2  = (const float*)d_in[4];
    const float* Wb  = (const float*)d_in[5];
    const float* bbv = (const float*)d_in[6];
    const float* Wn  = (const float*)d_in[7];
    const float* bnv = (const float*)d_in[8];
    const float* osc = (const float*)d_in[9];
    const float* obi = (const float*)d_in[10];
    const float* noise = (const float*)d_in[11];
    float* out = (float*)d_out;

    precompute_kernel<<<BB / 16, 256>>>(z, W1, b1, Wb, bbv, Wn, bnv);
    sde_kernel<<<BB / 16, 256>>>(W1, W2, b2, noise, osc, obi, out);
}

// round 12
// speedup vs baseline: 1.6159x; 1.6159x over previous
#include <cuda_runtime.h>
#include <cuda_fp16.h>
#include <math.h>

#define BB 16384
#define SS 16
#define NSTEPS 50
#define LATENT 128
#define HID 64
#define DTC 0.02f
#define SQRT_DT 0.14142135623730951f
#define LOG2E 1.4426950408889634f
#define LN2 0.6931471805599453f
#define EXPM50 1.9287498479639178e-22f /* exp(-50) */

// Scratch (no cudaMalloc allowed)
__device__ unsigned g_zch[BB * 32]; // per-b hidden bias, f16x2-packed pairs (32 pairs = 64 units)
__device__ float g_halfb[BB];       // 0.5*boundary
__device__ float g_ndt[BB];         // non-decision time

__device__ __forceinline__ float ex2f(float v) {
    float r; asm("ex2.approx.f32 %0, %1;" : "=f"(r) : "f"(v)); return r;
}
__device__ __forceinline__ float lg2f(float v) {
    float r; asm("lg2.approx.f32 %0, %1;" : "=f"(r) : "f"(v)); return r;
}
__device__ __forceinline__ float tanhapx(float v) {
    float r; asm("tanh.approx.f32 %0, %1;" : "=f"(r) : "f"(v)); return r;
}
__device__ __forceinline__ half2 tanh2h(half2 x) {
    unsigned xi = *reinterpret_cast<unsigned*>(&x);
    unsigned r;
    asm("tanh.approx.f16x2 %0, %1;" : "=r"(r) : "r"(xi));
    return *reinterpret_cast<half2*>(&r);
}
__device__ __forceinline__ half2 u2h(unsigned v) {
    return *reinterpret_cast<half2*>(&v);
}
__device__ __forceinline__ unsigned h2u(half2 v) {
    return *reinterpret_cast<unsigned*>(&v);
}
// Sum the two f16 halves of v as f32, using ALU-pipe bit-expansion
// (exact for normal f16; subnormals introduce <= 6.1e-5 abs error).
__device__ __forceinline__ float h2sum(half2 v) {
    unsigned r = *reinterpret_cast<unsigned*>(&v);
    unsigned lo = ((r << 16) & 0x80000000u) | (((r & 0x7FFFu) << 13) + 0x38000000u);
    unsigned hi = (r & 0x80000000u) | (((r >> 3) & 0x0FFFE000u) + 0x38000000u);
    return __uint_as_float(lo) + __uint_as_float(hi);
}
__device__ __forceinline__ float fix_out(float v) {
    if (isnan(v)) return 0.0f;
    return fminf(fmaxf(v, -3.402823466e38f), 3.402823466e38f);
}

// ---------------------------------------------------------------------------
// Precompute: zc[b][j] = b1[j] + sum_k z[b,k]*W1[j,2+k], stored f16x2-packed;
// boundary & ndt per b.
// ---------------------------------------------------------------------------
__global__ __launch_bounds__(256) void precompute_kernel(
    const float* __restrict__ z,  const float* __restrict__ W1,
    const float* __restrict__ b1, const float* __restrict__ Wb,
    const float* __restrict__ bbv, const float* __restrict__ Wn,
    const float* __restrict__ bnv)
{
    __shared__ __align__(16) float sW[HID * 130];   // whole W1, 33.3KB
    __shared__ __align__(16) float sz[16 * LATENT]; // 16 z rows, 8KB
    const int tid = threadIdx.x;
    const int b0 = blockIdx.x * 16;

    for (int i = tid; i < HID * 130; i += 256) sW[i] = W1[i];
    for (int i = tid; i < 16 * LATENT; i += 256) sz[i] = z[b0 * LATENT + i];
    __syncthreads();

    const int j = tid & 63;
    const int bg = tid >> 6;   // 0..3, each handles 4 b's
    const float* wrow = sW + j * 130 + 2;
    float a0, a1, a2, a3;
    a0 = a1 = a2 = a3 = b1[j];
    const float* z0 = sz + (bg * 4 + 0) * LATENT;
    const float* z1 = sz + (bg * 4 + 1) * LATENT;
    const float* z2 = sz + (bg * 4 + 2) * LATENT;
    const float* z3 = sz + (bg * 4 + 3) * LATENT;
    #pragma unroll 8
    for (int k = 0; k < LATENT; k += 4) {
        float w0 = wrow[k], w1 = wrow[k + 1], w2 = wrow[k + 2], w3 = wrow[k + 3];
        float4 q0 = *(const float4*)(z0 + k);
        float4 q1 = *(const float4*)(z1 + k);
        float4 q2 = *(const float4*)(z2 + k);
        float4 q3 = *(const float4*)(z3 + k);
        a0 = fmaf(w0, q0.x, a0); a0 = fmaf(w1, q0.y, a0); a0 = fmaf(w2, q0.z, a0); a0 = fmaf(w3, q0.w, a0);
        a1 = fmaf(w0, q1.x, a1); a1 = fmaf(w1, q1.y, a1); a1 = fmaf(w2, q1.z, a1); a1 = fmaf(w3, q1.w, a1);
        a2 = fmaf(w0, q2.x, a2); a2 = fmaf(w1, q2.y, a2); a2 = fmaf(w2, q2.z, a2); a2 = fmaf(w3, q2.w, a2);
        a3 = fmaf(w0, q3.x, a3); a3 = fmaf(w1, q3.y, a3); a3 = fmaf(w2, q3.z, a3); a3 = fmaf(w3, q3.w, a3);
    }

    // pack (j, j+1) pairs into f16x2 via partner shuffle; even j stores
    const float p0 = __shfl_xor_sync(0xffffffffu, a0, 1);
    const float p1 = __shfl_xor_sync(0xffffffffu, a1, 1);
    const float p2 = __shfl_xor_sync(0xffffffffu, a2, 1);
    const float p3 = __shfl_xor_sync(0xffffffffu, a3, 1);
    if ((j & 1) == 0) {
        const int col = j >> 1;   // 0..31
        half2 h0 = __floats2half2_rn(a0, p0);
        half2 h1 = __floats2half2_rn(a1, p1);
        half2 h2v = __floats2half2_rn(a2, p2);
        half2 h3 = __floats2half2_rn(a3, p3);
        g_zch[(b0 + bg * 4 + 0) * 32 + col] = h2u(h0);
        g_zch[(b0 + bg * 4 + 1) * 32 + col] = h2u(h1);
        g_zch[(b0 + bg * 4 + 2) * 32 + col] = h2u(h2v);
        g_zch[(b0 + bg * 4 + 3) * 32 + col] = h2u(h3);
    }

    if (tid < 32) {
        const int bl = tid >> 1;
        const int isn = tid & 1;
        const float* wv = isn ? Wn : Wb;
        const float* zz = sz + bl * LATENT;
        float acc = isn ? bnv[0] : bbv[0];
        #pragma unroll 8
        for (int k = 0; k < LATENT; k++) acc = fmaf(wv[k], zz[k], acc);
        float sp = fmaxf(acc, 0.0f) + log1pf(expf(-fabsf(acc)));
        if (isn) g_ndt[b0 + bl] = sp + 0.05f;
        else     g_halfb[b0 + bl] = 0.5f * (sp + 0.3f);
    }
}

// ---------------------------------------------------------------------------
// Main SDE kernel. TWO LANES PER SIM: lane half h owns 32 of 64 hidden units
// (16 f16x2 pairs) with ALL weights in registers (5 x 16 = 80 u32 regs).
// One warp = one b = 16 sims. Layer 1 entirely f16 (HFMA2 +
// tanh.approx.f16x2); one xor-1 shuffle pair per step completes the dot;
// pair lanes then carry identical state (no broadcast needed). Tail in f32.
// Final mean/std via warp butterflies (each sim duplicated on 2 lanes).
// Block 256 = 8 b's.
// ---------------------------------------------------------------------------
__global__ __launch_bounds__(256, 2) void sde_kernel(
    const float* __restrict__ W1, const float* __restrict__ W2,
    const float* __restrict__ b2, const float* __restrict__ noise,
    const float* __restrict__ osc, const float* __restrict__ obi,
    float* __restrict__ out)
{
    const int tid  = threadIdx.x;
    const int lane = tid & 31;
    const int w    = tid >> 5;        // warp 0..7
    const int b    = blockIdx.x * 8 + w;
    const int s    = lane >> 1;       // sim 0..15
    const int half = lane & 1;        // unit-half
    const int jbase = half * 32;

    // weights: 16 f16x2 pairs each = 80 u32 regs
    half2 w1x2[16], w1t2[16], zc2[16], w2a2[16], w2b2[16];
    #pragma unroll
    for (int p = 0; p < 16; p++) {
        const int j = jbase + p * 2;
        w1x2[p] = __floats2half2_rn(W1[j * 130],     W1[(j + 1) * 130]);
        w1t2[p] = __floats2half2_rn(W1[j * 130 + 1], W1[(j + 1) * 130 + 1]);
        zc2[p]  = u2h(g_zch[b * 32 + half * 16 + p]);
        w2a2[p] = __floats2half2_rn(W2[j],       W2[j + 1]);
        w2b2[p] = __floats2half2_rn(W2[HID + j], W2[HID + j + 1]);
    }
    const float b2x = b2[0], b2y = b2[1];
    const float half_b = g_halfb[b];
    const half2 hzero = __floats2half2_rn(0.0f, 0.0f);

    float x = 0.0f, p_surv = 1.0f, exp_rt = 0.0f, exp_corr = 0.0f;
    const int nidx = b * SS + s;
    float nz = noise[nidx];

    #pragma unroll 1
    for (int k = 0; k < NSTEPS; k++) {
        const int k1 = (k + 1 < NSTEPS) ? (k + 1) : (NSTEPS - 1);
        const float nz_next = noise[k1 * (BB * SS) + nidx];  // prefetch
        const float tk = (float)k * DTC;
        const half2 tkh = __float2half2_rn(tk);
        const half2 xh  = __float2half2_rn(x);

        half2 da0 = hzero, db0 = hzero, da1 = hzero, db1 = hzero;
        #pragma unroll
        for (int p = 0; p < 16; p += 2) {
            const half2 base0 = __hfma2(tkh, w1t2[p],     zc2[p]);
            const half2 base1 = __hfma2(tkh, w1t2[p + 1], zc2[p + 1]);
            const half2 u0 = __hfma2(xh, w1x2[p],     base0);
            const half2 u1 = __hfma2(xh, w1x2[p + 1], base1);
            const half2 h0 = tanh2h(u0);
            const half2 h1 = tanh2h(u1);
            da0 = __hfma2(h0, w2a2[p],     da0);
            db0 = __hfma2(h0, w2b2[p],     db0);
            da1 = __hfma2(h1, w2a2[p + 1], da1);
            db1 = __hfma2(h1, w2b2[p + 1], db1);
        }
        float pd = h2sum(da0) + h2sum(da1);
        float pf = h2sum(db0) + h2sum(db1);
        // combine the two unit-halves of this sim; result identical on both
        pd += __shfl_xor_sync(0xffffffffu, pd, 1);
        pf += __shfl_xor_sync(0xffffffffu, pf, 1);

        const float dyn0 = pd + b2x;
        const float dyn1 = pf + b2y;
        const float drift = fminf(fmaxf(dyn0, -5.0f), 5.0f);
        // softplus(dyn1) = max(v,0) + ln(1 + e^{-|v|})
        const float e1 = ex2f(-fabsf(dyn1) * LOG2E);
        const float sp = fmaxf(dyn1, 0.0f) + lg2f(1.0f + e1) * LN2;
        const float diff = sp + 0.1f;

        x = fmaf(diff * SQRT_DT, nz, fmaf(drift, DTC, x));
        x = fminf(fmaxf(x, -10.0f), 10.0f);

        const float dist = fabsf(x) - half_b;
        // sigmoid(20*dist) = 0.5 + 0.5*tanh(10*dist)
        const float sg = fmaf(0.5f, tanhapx(10.0f * dist), 0.5f);
        const float hz = fminf(fmaxf(sg, 0.0f), 0.99f);
        const float sb = fmaxf(p_surv, EXPM50);
        const float cp = sb * hz;
        p_surv = p_surv * (1.0f - hz);
        exp_rt = fmaf(cp, tk + DTC, exp_rt);
        exp_corr += (x > 0.0f) ? cp : 0.0f;

        nz = nz_next;
    }

    const float rem = fmaxf(p_surv, EXPM50);
    exp_rt  = fmaf(rem, (float)NSTEPS * DTC, exp_rt);
    exp_corr = fmaf(rem, 0.5f, exp_corr);
    const float rtms = (exp_rt + g_ndt[b]) * 1000.0f;

    // warp-wide stats; each sim appears on 2 lanes, so sums are 2x sim-sums
    float srt = rtms;
    float scr = exp_corr;
    #pragma unroll
    for (int off = 1; off < 32; off <<= 1) {
        srt += __shfl_xor_sync(0xffffffffu, srt, off);
        scr += __shfl_xor_sync(0xffffffffu, scr, off);
    }
    const float m = srt * (1.0f / 32.0f);
    const float c = scr * (1.0f / 32.0f);
    const float d = rtms - m;
    float v = d * d;
    #pragma unroll
    for (int off = 1; off < 32; off <<= 1) {
        v += __shfl_xor_sync(0xffffffffu, v, off);
    }

    if (lane == 0) {
        const float sd = sqrtf(v * (1.0f / 30.0f));  // 2x-dup, ddof=1
        const float o0 = m * osc[0] + obi[0];
        const float o1 = (sd + 0.001f) * osc[1] + obi[1];
        const float o2 = c * osc[2] + obi[2];
        out[b * 3 + 0] = fix_out(o0);
        out[b * 3 + 1] = fix_out(o1);
        out[b * 3 + 2] = fix_out(o2);
    }
}

extern "C" void kernel_launch(void* const* d_in, const int* in_sizes, int n_in,
                              void* d_out, int out_size)
{
    const float* z   = (const float*)d_in[0];
    const float* W1  = (const float*)d_in[1];
    const float* b1  = (const float*)d_in[2];
    const float* W2  = (const float*)d_in[3];
    const float* b2  = (const float*)d_in[4];
    const float* Wb  = (const float*)d_in[5];
    const float* bbv = (const float*)d_in[6];
    const float* Wn  = (const float*)d_in[7];
    const float* bnv = (const float*)d_in[8];
    const float* osc = (const float*)d_in[9];
    const float* obi = (const float*)d_in[10];
    const float* noise = (const float*)d_in[11];
    float* out = (float*)d_out;

    precompute_kernel<<<BB / 16, 256>>>(z, W1, b1, Wb, bbv, Wn, bnv);
    sde_kernel<<<BB / 8, 256>>>(W1, W2, b2, noise, osc, obi, out);
}

// round 13
// speedup vs baseline: 1.8789x; 1.1627x over previous
#include <cuda_runtime.h>
#include <cuda_fp16.h>
#include <math.h>

#define BB 16384
#define SS 16
#define NSTEPS 50
#define LATENT 128
#define HID 64
#define DTC 0.02f
#define SQRT_DT 0.14142135623730951f
#define LOG2E 1.4426950408889634f
#define LN2 0.6931471805599453f
#define EXPM50 1.9287498479639178e-22f /* exp(-50) */

// Scratch (no cudaMalloc allowed)
__device__ unsigned g_zch[BB * 32]; // per-b hidden bias, f16x2-packed pairs (32 pairs = 64 units)
__device__ float g_halfb[BB];       // 0.5*boundary
__device__ float g_ndt[BB];         // non-decision time

__device__ __forceinline__ float ex2f(float v) {
    float r; asm("ex2.approx.f32 %0, %1;" : "=f"(r) : "f"(v)); return r;
}
__device__ __forceinline__ float lg2f(float v) {
    float r; asm("lg2.approx.f32 %0, %1;" : "=f"(r) : "f"(v)); return r;
}
__device__ __forceinline__ float tanhapx(float v) {
    float r; asm("tanh.approx.f32 %0, %1;" : "=f"(r) : "f"(v)); return r;
}
__device__ __forceinline__ half2 tanh2h(half2 x) {
    unsigned xi = *reinterpret_cast<unsigned*>(&x);
    unsigned r;
    asm("tanh.approx.f16x2 %0, %1;" : "=r"(r) : "r"(xi));
    return *reinterpret_cast<half2*>(&r);
}
__device__ __forceinline__ half2 u2h(unsigned v) {
    return *reinterpret_cast<half2*>(&v);
}
__device__ __forceinline__ unsigned h2u(half2 v) {
    return *reinterpret_cast<unsigned*>(&v);
}
// Sum the two f16 halves of v as f32, using ALU-pipe bit-expansion
// (exact for normal f16; subnormals introduce <= 6.1e-5 abs error).
__device__ __forceinline__ float h2sum(half2 v) {
    unsigned r = *reinterpret_cast<unsigned*>(&v);
    unsigned lo = ((r << 16) & 0x80000000u) | (((r & 0x7FFFu) << 13) + 0x38000000u);
    unsigned hi = (r & 0x80000000u) | (((r >> 3) & 0x0FFFE000u) + 0x38000000u);
    return __uint_as_float(lo) + __uint_as_float(hi);
}
__device__ __forceinline__ float fix_out(float v) {
    if (isnan(v)) return 0.0f;
    return fminf(fmaxf(v, -3.402823466e38f), 3.402823466e38f);
}

// ---------------------------------------------------------------------------
// Precompute: zc[b][j] = b1[j] + sum_k z[b,k]*W1[j,2+k], stored f16x2-packed;
// boundary & ndt per b.
// ---------------------------------------------------------------------------
__global__ __launch_bounds__(256) void precompute_kernel(
    const float* __restrict__ z,  const float* __restrict__ W1,
    const float* __restrict__ b1, const float* __restrict__ Wb,
    const float* __restrict__ bbv, const float* __restrict__ Wn,
    const float* __restrict__ bnv)
{
    __shared__ __align__(16) float sW[HID * 130];   // whole W1, 33.3KB
    __shared__ __align__(16) float sz[16 * LATENT]; // 16 z rows, 8KB
    const int tid = threadIdx.x;
    const int b0 = blockIdx.x * 16;

    for (int i = tid; i < HID * 130; i += 256) sW[i] = W1[i];
    for (int i = tid; i < 16 * LATENT; i += 256) sz[i] = z[b0 * LATENT + i];
    __syncthreads();

    const int j = tid & 63;
    const int bg = tid >> 6;   // 0..3, each handles 4 b's
    const float* wrow = sW + j * 130 + 2;
    float a0, a1, a2, a3;
    a0 = a1 = a2 = a3 = b1[j];
    const float* z0 = sz + (bg * 4 + 0) * LATENT;
    const float* z1 = sz + (bg * 4 + 1) * LATENT;
    const float* z2 = sz + (bg * 4 + 2) * LATENT;
    const float* z3 = sz + (bg * 4 + 3) * LATENT;
    #pragma unroll 8
    for (int k = 0; k < LATENT; k += 4) {
        float w0 = wrow[k], w1 = wrow[k + 1], w2 = wrow[k + 2], w3 = wrow[k + 3];
        float4 q0 = *(const float4*)(z0 + k);
        float4 q1 = *(const float4*)(z1 + k);
        float4 q2 = *(const float4*)(z2 + k);
        float4 q3 = *(const float4*)(z3 + k);
        a0 = fmaf(w0, q0.x, a0); a0 = fmaf(w1, q0.y, a0); a0 = fmaf(w2, q0.z, a0); a0 = fmaf(w3, q0.w, a0);
        a1 = fmaf(w0, q1.x, a1); a1 = fmaf(w1, q1.y, a1); a1 = fmaf(w2, q1.z, a1); a1 = fmaf(w3, q1.w, a1);
        a2 = fmaf(w0, q2.x, a2); a2 = fmaf(w1, q2.y, a2); a2 = fmaf(w2, q2.z, a2); a2 = fmaf(w3, q2.w, a2);
        a3 = fmaf(w0, q3.x, a3); a3 = fmaf(w1, q3.y, a3); a3 = fmaf(w2, q3.z, a3); a3 = fmaf(w3, q3.w, a3);
    }

    // pack (j, j+1) pairs into f16x2 via partner shuffle; even j stores
    const float p0 = __shfl_xor_sync(0xffffffffu, a0, 1);
    const float p1 = __shfl_xor_sync(0xffffffffu, a1, 1);
    const float p2 = __shfl_xor_sync(0xffffffffu, a2, 1);
    const float p3 = __shfl_xor_sync(0xffffffffu, a3, 1);
    if ((j & 1) == 0) {
        const int col = j >> 1;   // 0..31
        half2 h0 = __floats2half2_rn(a0, p0);
        half2 h1 = __floats2half2_rn(a1, p1);
        half2 h2v = __floats2half2_rn(a2, p2);
        half2 h3 = __floats2half2_rn(a3, p3);
        g_zch[(b0 + bg * 4 + 0) * 32 + col] = h2u(h0);
        g_zch[(b0 + bg * 4 + 1) * 32 + col] = h2u(h1);
        g_zch[(b0 + bg * 4 + 2) * 32 + col] = h2u(h2v);
        g_zch[(b0 + bg * 4 + 3) * 32 + col] = h2u(h3);
    }

    if (tid < 32) {
        const int bl = tid >> 1;
        const int isn = tid & 1;
        const float* wv = isn ? Wn : Wb;
        const float* zz = sz + bl * LATENT;
        float acc = isn ? bnv[0] : bbv[0];
        #pragma unroll 8
        for (int k = 0; k < LATENT; k++) acc = fmaf(wv[k], zz[k], acc);
        float sp = fmaxf(acc, 0.0f) + log1pf(expf(-fabsf(acc)));
        if (isn) g_ndt[b0 + bl] = sp + 0.05f;
        else     g_halfb[b0 + bl] = 0.5f * (sp + 0.3f);
    }
}

// ---------------------------------------------------------------------------
// Main SDE kernel. Lane pair (2q, 2q+1) serves TWO sims (s, s+8) of one b;
// each lane owns 32 of the 64 hidden units (16 f16x2 pairs) with ALL weights
// in registers (80 u32). The base = tk*w1t + zc HFMA2 is shared between the
// two sims; the two sims' chains interleave for 2x ILP. One xor-1 shuffle
// per sim completes the hidden dot; pair lanes then carry identical state.
// Warp = 16 pairs = 32 sims = 2 b's. Block 256 = 8 warps = 16 b's.
// ---------------------------------------------------------------------------
__global__ __launch_bounds__(256, 2) void sde_kernel(
    const float* __restrict__ W1, const float* __restrict__ W2,
    const float* __restrict__ b2, const float* __restrict__ noise,
    const float* __restrict__ osc, const float* __restrict__ obi,
    float* __restrict__ out)
{
    const int tid  = threadIdx.x;
    const int lane = tid & 31;
    const int w    = tid >> 5;        // warp 0..7
    const int q    = lane >> 1;       // pair 0..15
    const int half = lane & 1;        // unit-half
    const int b    = blockIdx.x * 16 + w * 2 + (q >> 3);
    const int sA   = q & 7;           // sim A
    const int jbase = half * 32;

    // weights: 16 f16x2 pairs each = 80 u32 regs
    half2 w1x2[16], w1t2[16], zc2[16], w2a2[16], w2b2[16];
    #pragma unroll
    for (int p = 0; p < 16; p++) {
        const int j = jbase + p * 2;
        w1x2[p] = __floats2half2_rn(W1[j * 130],     W1[(j + 1) * 130]);
        w1t2[p] = __floats2half2_rn(W1[j * 130 + 1], W1[(j + 1) * 130 + 1]);
        zc2[p]  = u2h(g_zch[b * 32 + half * 16 + p]);
        w2a2[p] = __floats2half2_rn(W2[j],       W2[j + 1]);
        w2b2[p] = __floats2half2_rn(W2[HID + j], W2[HID + j + 1]);
    }
    const float b2x = b2[0], b2y = b2[1];
    const float half_b = g_halfb[b];
    const half2 hzero = __floats2half2_rn(0.0f, 0.0f);

    float xA = 0.0f, pA = 1.0f, rtA = 0.0f, crA = 0.0f;
    float xB = 0.0f, pB = 1.0f, rtB = 0.0f, crB = 0.0f;
    const int nidxA = b * SS + sA;
    const int nidxB = nidxA + 8;
    float nzA = noise[nidxA];
    float nzB = noise[nidxB];

    #pragma unroll 1
    for (int k = 0; k < NSTEPS; k++) {
        const int k1 = (k + 1 < NSTEPS) ? (k + 1) : (NSTEPS - 1);
        const float nzA_n = noise[k1 * (BB * SS) + nidxA];
        const float nzB_n = noise[k1 * (BB * SS) + nidxB];
        const float tk = (float)k * DTC;
        const half2 tkh = __float2half2_rn(tk);
        const half2 xhA = __float2half2_rn(xA);
        const half2 xhB = __float2half2_rn(xB);

        half2 daA = hzero, dbA = hzero, daB = hzero, dbB = hzero;
        #pragma unroll
        for (int p = 0; p < 16; p++) {
            const half2 base = __hfma2(tkh, w1t2[p], zc2[p]);   // shared A/B
            const half2 uA = __hfma2(xhA, w1x2[p], base);
            const half2 uB = __hfma2(xhB, w1x2[p], base);
            const half2 hA = tanh2h(uA);
            const half2 hB = tanh2h(uB);
            daA = __hfma2(hA, w2a2[p], daA);
            dbA = __hfma2(hA, w2b2[p], dbA);
            daB = __hfma2(hB, w2a2[p], daB);
            dbB = __hfma2(hB, w2b2[p], dbB);
        }
        float pdA = h2sum(daA);
        float pfA = h2sum(dbA);
        float pdB = h2sum(daB);
        float pfB = h2sum(dbB);
        // combine the two unit-halves; results identical on both pair lanes
        pdA += __shfl_xor_sync(0xffffffffu, pdA, 1);
        pfA += __shfl_xor_sync(0xffffffffu, pfA, 1);
        pdB += __shfl_xor_sync(0xffffffffu, pdB, 1);
        pfB += __shfl_xor_sync(0xffffffffu, pfB, 1);

        // --- tail, sim A ---
        {
            const float dyn0 = pdA + b2x;
            const float dyn1 = pfA + b2y;
            const float drift = fminf(fmaxf(dyn0, -5.0f), 5.0f);
            const float e1 = ex2f(-fabsf(dyn1) * LOG2E);
            const float spv = fmaxf(dyn1, 0.0f) + lg2f(1.0f + e1) * LN2;
            const float diff = spv + 0.1f;
            xA = fmaf(diff * SQRT_DT, nzA, fmaf(drift, DTC, xA));
            xA = fminf(fmaxf(xA, -10.0f), 10.0f);
            const float dist = fabsf(xA) - half_b;
            const float sg = fmaf(0.5f, tanhapx(10.0f * dist), 0.5f);
            const float hz = fminf(fmaxf(sg, 0.0f), 0.99f);
            const float sb = fmaxf(pA, EXPM50);
            const float cp = sb * hz;
            pA = pA * (1.0f - hz);
            rtA = fmaf(cp, tk + DTC, rtA);
            crA += (xA > 0.0f) ? cp : 0.0f;
        }
        // --- tail, sim B ---
        {
            const float dyn0 = pdB + b2x;
            const float dyn1 = pfB + b2y;
            const float drift = fminf(fmaxf(dyn0, -5.0f), 5.0f);
            const float e1 = ex2f(-fabsf(dyn1) * LOG2E);
            const float spv = fmaxf(dyn1, 0.0f) + lg2f(1.0f + e1) * LN2;
            const float diff = spv + 0.1f;
            xB = fmaf(diff * SQRT_DT, nzB, fmaf(drift, DTC, xB));
            xB = fminf(fmaxf(xB, -10.0f), 10.0f);
            const float dist = fabsf(xB) - half_b;
            const float sg = fmaf(0.5f, tanhapx(10.0f * dist), 0.5f);
            const float hz = fminf(fmaxf(sg, 0.0f), 0.99f);
            const float sb = fmaxf(pB, EXPM50);
            const float cp = sb * hz;
            pB = pB * (1.0f - hz);
            rtB = fmaf(cp, tk + DTC, rtB);
            crB += (xB > 0.0f) ? cp : 0.0f;
        }

        nzA = nzA_n;
        nzB = nzB_n;
    }

    const float remA = fmaxf(pA, EXPM50);
    const float remB = fmaxf(pB, EXPM50);
    rtA = fmaf(remA, (float)NSTEPS * DTC, rtA);
    rtB = fmaf(remB, (float)NSTEPS * DTC, rtB);
    crA = fmaf(remA, 0.5f, crA);
    crB = fmaf(remB, 0.5f, crB);
    const float ndt = g_ndt[b];
    const float rtmsA = (rtA + ndt) * 1000.0f;
    const float rtmsB = (rtB + ndt) * 1000.0f;

    // stats per b within each 16-lane group (lanes 0-15: b0, 16-31: b1).
    // Each sim's result is duplicated on the 2 pair lanes -> sums are 2x.
    float srt = rtmsA + rtmsB;
    float scr = crA + crB;
    #pragma unroll
    for (int off = 1; off < 16; off <<= 1) {
        srt += __shfl_xor_sync(0xffffffffu, srt, off);
        scr += __shfl_xor_sync(0xffffffffu, scr, off);
    }
    const float m = srt * (1.0f / 32.0f);
    const float c = scr * (1.0f / 32.0f);
    const float dA = rtmsA - m;
    const float dB = rtmsB - m;
    float v = dA * dA + dB * dB;
    #pragma unroll
    for (int off = 1; off < 16; off <<= 1) {
        v += __shfl_xor_sync(0xffffffffu, v, off);
    }

    if ((lane & 15) == 0) {
        const float sd = sqrtf(v * (1.0f / 30.0f));  // 2x-dup, ddof=1
        const float o0 = m * osc[0] + obi[0];
        const float o1 = (sd + 0.001f) * osc[1] + obi[1];
        const float o2 = c * osc[2] + obi[2];
        out[b * 3 + 0] = fix_out(o0);
        out[b * 3 + 1] = fix_out(o1);
        out[b * 3 + 2] = fix_out(o2);
    }
}

extern "C" void kernel_launch(void* const* d_in, const int* in_sizes, int n_in,
                              void* d_out, int out_size)
{
    const float* z   = (const float*)d_in[0];
    const float* W1  = (const float*)d_in[1];
    const float* b1  = (const float*)d_in[2];
    const float* W2  = (const float*)d_in[3];
    const float* b2  = (const float*)d_in[4];
    const float* Wb  = (const float*)d_in[5];
    const float* bbv = (const float*)d_in[6];
    const float* Wn  = (const float*)d_in[7];
    const float* bnv = (const float*)d_in[8];
    const float* osc = (const float*)d_in[9];
    const float* obi = (const float*)d_in[10];
    const float* noise = (const float*)d_in[11];
    float* out = (float*)d_out;

    precompute_kernel<<<BB / 16, 256>>>(z, W1, b1, Wb, bbv, Wn, bnv);
    sde_kernel<<<BB / 16, 256>>>(W1, W2, b2, noise, osc, obi, out);
}

// round 14
// speedup vs baseline: 1.9212x; 1.0225x over previous
#include <cuda_runtime.h>
#include <cuda_fp16.h>
#include <math.h>

#define BB 16384
#define SS 16
#define NSTEPS 50
#define LATENT 128
#define HID 64
#define DTC 0.02f
#define SQRT_DT 0.14142135623730951f
#define LOG2E 1.4426950408889634f
#define LN2 0.6931471805599453f
#define EXPM50 1.9287498479639178e-22f /* exp(-50) */

// Scratch (no cudaMalloc allowed)
__device__ unsigned g_zch[BB * 32]; // per-b hidden bias, f16x2-packed pairs (32 pairs = 64 units)
__device__ float g_halfb[BB];       // 0.5*boundary
__device__ float g_ndt[BB];         // non-decision time

__device__ __forceinline__ float ex2f(float v) {
    float r; asm("ex2.approx.f32 %0, %1;" : "=f"(r) : "f"(v)); return r;
}
__device__ __forceinline__ float lg2f(float v) {
    float r; asm("lg2.approx.f32 %0, %1;" : "=f"(r) : "f"(v)); return r;
}
__device__ __forceinline__ float tanhapx(float v) {
    float r; asm("tanh.approx.f32 %0, %1;" : "=f"(r) : "f"(v)); return r;
}
__device__ __forceinline__ half2 tanh2h(half2 x) {
    unsigned xi = *reinterpret_cast<unsigned*>(&x);
    unsigned r;
    asm("tanh.approx.f16x2 %0, %1;" : "=r"(r) : "r"(xi));
    return *reinterpret_cast<half2*>(&r);
}
__device__ __forceinline__ half2 u2h(unsigned v) {
    return *reinterpret_cast<half2*>(&v);
}
__device__ __forceinline__ unsigned h2u(half2 v) {
    return *reinterpret_cast<unsigned*>(&v);
}
// Sum the two f16 halves of v as f32, using ALU-pipe bit-expansion
// (exact for normal f16; subnormals introduce <= 6.1e-5 abs error).
__device__ __forceinline__ float h2sum(half2 v) {
    unsigned r = *reinterpret_cast<unsigned*>(&v);
    unsigned lo = ((r << 16) & 0x80000000u) | (((r & 0x7FFFu) << 13) + 0x38000000u);
    unsigned hi = (r & 0x80000000u) | (((r >> 3) & 0x0FFFE000u) + 0x38000000u);
    return __uint_as_float(lo) + __uint_as_float(hi);
}
__device__ __forceinline__ float fix_out(float v) {
    if (isnan(v)) return 0.0f;
    return fminf(fmaxf(v, -3.402823466e38f), 3.402823466e38f);
}

// ---------------------------------------------------------------------------
// Precompute: zc[b][j] = b1[j] + sum_k z[b,k]*W1[j,2+k], stored f16x2-packed;
// boundary & ndt per b.
// ---------------------------------------------------------------------------
__global__ __launch_bounds__(256) void precompute_kernel(
    const float* __restrict__ z,  const float* __restrict__ W1,
    const float* __restrict__ b1, const float* __restrict__ Wb,
    const float* __restrict__ bbv, const float* __restrict__ Wn,
    const float* __restrict__ bnv)
{
    __shared__ __align__(16) float sW[HID * 130];   // whole W1, 33.3KB
    __shared__ __align__(16) float sz[16 * LATENT]; // 16 z rows, 8KB
    const int tid = threadIdx.x;
    const int b0 = blockIdx.x * 16;

    for (int i = tid; i < HID * 130; i += 256) sW[i] = W1[i];
    for (int i = tid; i < 16 * LATENT; i += 256) sz[i] = z[b0 * LATENT + i];
    __syncthreads();

    const int j = tid & 63;
    const int bg = tid >> 6;   // 0..3, each handles 4 b's
    const float* wrow = sW + j * 130 + 2;
    float a0, a1, a2, a3;
    a0 = a1 = a2 = a3 = b1[j];
    const float* z0 = sz + (bg * 4 + 0) * LATENT;
    const float* z1 = sz + (bg * 4 + 1) * LATENT;
    const float* z2 = sz + (bg * 4 + 2) * LATENT;
    const float* z3 = sz + (bg * 4 + 3) * LATENT;
    #pragma unroll 8
    for (int k = 0; k < LATENT; k += 4) {
        float w0 = wrow[k], w1 = wrow[k + 1], w2 = wrow[k + 2], w3 = wrow[k + 3];
        float4 q0 = *(const float4*)(z0 + k);
        float4 q1 = *(const float4*)(z1 + k);
        float4 q2 = *(const float4*)(z2 + k);
        float4 q3 = *(const float4*)(z3 + k);
        a0 = fmaf(w0, q0.x, a0); a0 = fmaf(w1, q0.y, a0); a0 = fmaf(w2, q0.z, a0); a0 = fmaf(w3, q0.w, a0);
        a1 = fmaf(w0, q1.x, a1); a1 = fmaf(w1, q1.y, a1); a1 = fmaf(w2, q1.z, a1); a1 = fmaf(w3, q1.w, a1);
        a2 = fmaf(w0, q2.x, a2); a2 = fmaf(w1, q2.y, a2); a2 = fmaf(w2, q2.z, a2); a2 = fmaf(w3, q2.w, a2);
        a3 = fmaf(w0, q3.x, a3); a3 = fmaf(w1, q3.y, a3); a3 = fmaf(w2, q3.z, a3); a3 = fmaf(w3, q3.w, a3);
    }

    // pack (j, j+1) pairs into f16x2 via partner shuffle; even j stores
    const float p0 = __shfl_xor_sync(0xffffffffu, a0, 1);
    const float p1 = __shfl_xor_sync(0xffffffffu, a1, 1);
    const float p2 = __shfl_xor_sync(0xffffffffu, a2, 1);
    const float p3 = __shfl_xor_sync(0xffffffffu, a3, 1);
    if ((j & 1) == 0) {
        const int col = j >> 1;   // 0..31
        half2 h0 = __floats2half2_rn(a0, p0);
        half2 h1 = __floats2half2_rn(a1, p1);
        half2 h2v = __floats2half2_rn(a2, p2);
        half2 h3 = __floats2half2_rn(a3, p3);
        g_zch[(b0 + bg * 4 + 0) * 32 + col] = h2u(h0);
        g_zch[(b0 + bg * 4 + 1) * 32 + col] = h2u(h1);
        g_zch[(b0 + bg * 4 + 2) * 32 + col] = h2u(h2v);
        g_zch[(b0 + bg * 4 + 3) * 32 + col] = h2u(h3);
    }

    if (tid < 32) {
        const int bl = tid >> 1;
        const int isn = tid & 1;
        const float* wv = isn ? Wn : Wb;
        const float* zz = sz + bl * LATENT;
        float acc = isn ? bnv[0] : bbv[0];
        #pragma unroll 8
        for (int k = 0; k < LATENT; k++) acc = fmaf(wv[k], zz[k], acc);
        float sp = fmaxf(acc, 0.0f) + log1pf(expf(-fabsf(acc)));
        if (isn) g_ndt[b0 + bl] = sp + 0.05f;
        else     g_halfb[b0 + bl] = 0.5f * (sp + 0.3f);
    }
}

// ---------------------------------------------------------------------------
// Main SDE kernel. Lane pair (2q, 2q+1) serves two sims of one b; each lane
// owns 32 of 64 hidden units (16 f16x2 pairs, ALL weights in registers) and
// evaluates BOTH sims' hidden layers (shared base HFMA2), but owns the tail
// and survival state of only ONE sim (even lane -> sim A = q&7, odd lane ->
// sim B = (q&7)+8). Reduction: packed-f16 exchange (SEL+SHFL+HADD2), then
// h2sum only for my sim. One x-exchange shuffle per step. Warp = 32 sims =
// 2 b's; each lane ends owning exactly one sim's stats.
// Block 256 = 16 b's.
// ---------------------------------------------------------------------------
__global__ __launch_bounds__(256, 2) void sde_kernel(
    const float* __restrict__ W1, const float* __restrict__ W2,
    const float* __restrict__ b2, const float* __restrict__ noise,
    const float* __restrict__ osc, const float* __restrict__ obi,
    float* __restrict__ out)
{
    const int tid  = threadIdx.x;
    const int lane = tid & 31;
    const int w    = tid >> 5;        // warp 0..7
    const int q    = lane >> 1;       // pair 0..15
    const int half = lane & 1;        // unit-half AND tail-parity
    const int b    = blockIdx.x * 16 + w * 2 + (q >> 3);
    const int jbase = half * 32;

    // weights: 16 f16x2 pairs each = 80 u32 regs
    half2 w1x2[16], w1t2[16], zc2[16], w2a2[16], w2b2[16];
    #pragma unroll
    for (int p = 0; p < 16; p++) {
        const int j = jbase + p * 2;
        w1x2[p] = __floats2half2_rn(W1[j * 130],     W1[(j + 1) * 130]);
        w1t2[p] = __floats2half2_rn(W1[j * 130 + 1], W1[(j + 1) * 130 + 1]);
        zc2[p]  = u2h(g_zch[b * 32 + half * 16 + p]);
        w2a2[p] = __floats2half2_rn(W2[j],       W2[j + 1]);
        w2b2[p] = __floats2half2_rn(W2[HID + j], W2[HID + j + 1]);
    }
    const float b2x = b2[0], b2y = b2[1];
    const float half_b = g_halfb[b];
    const half2 hzero = __floats2half2_rn(0.0f, 0.0f);

    // my sim: even lane -> sA = q&7; odd lane -> sA+8
    const int nidx = b * SS + (q & 7) + half * 8;
    float x_my = 0.0f, p_my = 1.0f, rt_my = 0.0f, cr_my = 0.0f;
    float xA_f = 0.0f, xB_f = 0.0f;   // both sims' states (tracked via exchange)
    float nz_my = noise[nidx];

    #pragma unroll 1
    for (int k = 0; k < NSTEPS; k++) {
        const int k1 = (k + 1 < NSTEPS) ? (k + 1) : (NSTEPS - 1);
        const float nz_next = noise[k1 * (BB * SS) + nidx];
        const float tk = (float)k * DTC;
        const half2 tkh = __float2half2_rn(tk);
        const half2 xhA = __float2half2_rn(xA_f);
        const half2 xhB = __float2half2_rn(xB_f);

        half2 daA = hzero, dbA = hzero, daB = hzero, dbB = hzero;
        #pragma unroll
        for (int p = 0; p < 16; p++) {
            const half2 base = __hfma2(tkh, w1t2[p], zc2[p]);   // shared A/B
            const half2 uA = __hfma2(xhA, w1x2[p], base);
            const half2 uB = __hfma2(xhB, w1x2[p], base);
            const half2 hA = tanh2h(uA);
            const half2 hB = tanh2h(uB);
            daA = __hfma2(hA, w2a2[p], daA);
            dbA = __hfma2(hA, w2b2[p], dbA);
            daB = __hfma2(hB, w2a2[p], daB);
            dbB = __hfma2(hB, w2b2[p], dbB);
        }
        // packed-f16 exchange: even sends its B-partials, odd its A-partials
        const unsigned da_send = half ? h2u(daA) : h2u(daB);
        const unsigned db_send = half ? h2u(dbA) : h2u(dbB);
        const unsigned da_recv = __shfl_xor_sync(0xffffffffu, da_send, 1);
        const unsigned db_recv = __shfl_xor_sync(0xffffffffu, db_send, 1);
        const half2 myda = __hadd2(half ? daB : daA, u2h(da_recv));
        const half2 mydb = __hadd2(half ? dbB : dbA, u2h(db_recv));
        const float pd = h2sum(myda);
        const float pf = h2sum(mydb);

        // --- tail for MY sim only ---
        const float dyn0 = pd + b2x;
        const float dyn1 = pf + b2y;
        const float drift = fminf(fmaxf(dyn0, -5.0f), 5.0f);
        const float e1 = ex2f(-fabsf(dyn1) * LOG2E);
        const float spv = fmaxf(dyn1, 0.0f) + lg2f(1.0f + e1) * LN2;
        const float diff = spv + 0.1f;
        x_my = fmaf(diff * SQRT_DT, nz_my, fmaf(drift, DTC, x_my));
        x_my = fminf(fmaxf(x_my, -10.0f), 10.0f);
        const float dist = fabsf(x_my) - half_b;
        const float sg = fmaf(0.5f, tanhapx(10.0f * dist), 0.5f);
        const float hz = fminf(fmaxf(sg, 0.0f), 0.99f);
        const float sb = fmaxf(p_my, EXPM50);
        const float cp = sb * hz;
        p_my = p_my * (1.0f - hz);
        rt_my = fmaf(cp, tk + DTC, rt_my);
        cr_my += (x_my > 0.0f) ? cp : 0.0f;

        // exchange updated x's
        const float x_oth = __shfl_xor_sync(0xffffffffu, x_my, 1);
        xA_f = half ? x_oth : x_my;
        xB_f = half ? x_my : x_oth;

        nz_my = nz_next;
    }

    const float rem = fmaxf(p_my, EXPM50);
    rt_my = fmaf(rem, (float)NSTEPS * DTC, rt_my);
    cr_my = fmaf(rem, 0.5f, cr_my);
    const float rtms = (rt_my + g_ndt[b]) * 1000.0f;

    // stats per b: each of the 16 lanes of a b-group owns exactly one sim
    float srt = rtms;
    float scr = cr_my;
    #pragma unroll
    for (int off = 1; off < 16; off <<= 1) {
        srt += __shfl_xor_sync(0xffffffffu, srt, off);
        scr += __shfl_xor_sync(0xffffffffu, scr, off);
    }
    const float m = srt * (1.0f / 16.0f);
    const float c = scr * (1.0f / 16.0f);
    const float d = rtms - m;
    float v = d * d;
    #pragma unroll
    for (int off = 1; off < 16; off <<= 1) {
        v += __shfl_xor_sync(0xffffffffu, v, off);
    }

    if ((lane & 15) == 0) {
        const float sd = sqrtf(v * (1.0f / 15.0f));  // ddof=1
        const float o0 = m * osc[0] + obi[0];
        const float o1 = (sd + 0.001f) * osc[1] + obi[1];
        const float o2 = c * osc[2] + obi[2];
        out[b * 3 + 0] = fix_out(o0);
        out[b * 3 + 1] = fix_out(o1);
        out[b * 3 + 2] = fix_out(o2);
    }
}

extern "C" void kernel_launch(void* const* d_in, const int* in_sizes, int n_in,
                              void* d_out, int out_size)
{
    const float* z   = (const float*)d_in[0];
    const float* W1  = (const float*)d_in[1];
    const float* b1  = (const float*)d_in[2];
    const float* W2  = (const float*)d_in[3];
    const float* b2  = (const float*)d_in[4];
    const float* Wb  = (const float*)d_in[5];
    const float* bbv = (const float*)d_in[6];
    const float* Wn  = (const float*)d_in[7];
    const float* bnv = (const float*)d_in[8];
    const float* osc = (const float*)d_in[9];
    const float* obi = (const float*)d_in[10];
    const float* noise = (const float*)d_in[11];
    float* out = (float*)d_out;

    precompute_kernel<<<BB / 16, 256>>>(z, W1, b1, Wb, bbv, Wn, bnv);
    sde_kernel<<<BB / 16, 256>>>(W1, W2, b2, noise, osc, obi, out);
}

// round 15
// speedup vs baseline: 1.9849x; 1.0332x over previous
#include <cuda_runtime.h>
#include <cuda_fp16.h>
#include <math.h>

#define BB 16384
#define SS 16
#define NSTEPS 50
#define LATENT 128
#define HID 64
#define DTC 0.02f
#define SQRT_DT 0.14142135623730951f
#define LOG2E 1.4426950408889634f
#define LN2 0.6931471805599453f
#define EXPM50 1.9287498479639178e-22f /* exp(-50) */

// Scratch (no cudaMalloc allowed)
__device__ unsigned g_zch[BB * 32]; // per-b hidden bias, f16x2-packed pairs (32 pairs = 64 units)
__device__ float g_halfb[BB];       // 0.5*boundary
__device__ float g_ndt[BB];         // non-decision time

__device__ __forceinline__ float ex2f(float v) {
    float r; asm("ex2.approx.f32 %0, %1;" : "=f"(r) : "f"(v)); return r;
}
__device__ __forceinline__ float lg2f(float v) {
    float r; asm("lg2.approx.f32 %0, %1;" : "=f"(r) : "f"(v)); return r;
}
__device__ __forceinline__ float tanhapx(float v) {
    float r; asm("tanh.approx.f32 %0, %1;" : "=f"(r) : "f"(v)); return r;
}
__device__ __forceinline__ half2 tanh2h(half2 x) {
    unsigned xi = *reinterpret_cast<unsigned*>(&x);
    unsigned r;
    asm("tanh.approx.f16x2 %0, %1;" : "=r"(r) : "r"(xi));
    return *reinterpret_cast<half2*>(&r);
}
__device__ __forceinline__ half2 u2h(unsigned v) {
    return *reinterpret_cast<half2*>(&v);
}
__device__ __forceinline__ unsigned h2u(half2 v) {
    return *reinterpret_cast<unsigned*>(&v);
}
// Sum the two f16 halves of v as f32, using ALU-pipe bit-expansion
// (exact for normal f16; subnormals introduce <= 6.1e-5 abs error).
__device__ __forceinline__ float h2sum(half2 v) {
    unsigned r = *reinterpret_cast<unsigned*>(&v);
    unsigned lo = ((r << 16) & 0x80000000u) | (((r & 0x7FFFu) << 13) + 0x38000000u);
    unsigned hi = (r & 0x80000000u) | (((r >> 3) & 0x0FFFE000u) + 0x38000000u);
    return __uint_as_float(lo) + __uint_as_float(hi);
}
__device__ __forceinline__ float fix_out(float v) {
    if (isnan(v)) return 0.0f;
    return fminf(fmaxf(v, -3.402823466e38f), 3.402823466e38f);
}

// ---------------------------------------------------------------------------
// Precompute: zc[b][j] = b1[j] + sum_k z[b,k]*W1[j,2+k], stored f16x2-packed;
// boundary & ndt per b.
// ---------------------------------------------------------------------------
__global__ __launch_bounds__(256) void precompute_kernel(
    const float* __restrict__ z,  const float* __restrict__ W1,
    const float* __restrict__ b1, const float* __restrict__ Wb,
    const float* __restrict__ bbv, const float* __restrict__ Wn,
    const float* __restrict__ bnv)
{
    __shared__ __align__(16) float sW[HID * 130];   // whole W1, 33.3KB
    __shared__ __align__(16) float sz[16 * LATENT]; // 16 z rows, 8KB
    const int tid = threadIdx.x;
    const int b0 = blockIdx.x * 16;

    for (int i = tid; i < HID * 130; i += 256) sW[i] = W1[i];
    for (int i = tid; i < 16 * LATENT; i += 256) sz[i] = z[b0 * LATENT + i];
    __syncthreads();

    const int j = tid & 63;
    const int bg = tid >> 6;   // 0..3, each handles 4 b's
    const float* wrow = sW + j * 130 + 2;
    float a0, a1, a2, a3;
    a0 = a1 = a2 = a3 = b1[j];
    const float* z0 = sz + (bg * 4 + 0) * LATENT;
    const float* z1 = sz + (bg * 4 + 1) * LATENT;
    const float* z2 = sz + (bg * 4 + 2) * LATENT;
    const float* z3 = sz + (bg * 4 + 3) * LATENT;
    #pragma unroll 8
    for (int k = 0; k < LATENT; k += 4) {
        float w0 = wrow[k], w1 = wrow[k + 1], w2 = wrow[k + 2], w3 = wrow[k + 3];
        float4 q0 = *(const float4*)(z0 + k);
        float4 q1 = *(const float4*)(z1 + k);
        float4 q2 = *(const float4*)(z2 + k);
        float4 q3 = *(const float4*)(z3 + k);
        a0 = fmaf(w0, q0.x, a0); a0 = fmaf(w1, q0.y, a0); a0 = fmaf(w2, q0.z, a0); a0 = fmaf(w3, q0.w, a0);
        a1 = fmaf(w0, q1.x, a1); a1 = fmaf(w1, q1.y, a1); a1 = fmaf(w2, q1.z, a1); a1 = fmaf(w3, q1.w, a1);
        a2 = fmaf(w0, q2.x, a2); a2 = fmaf(w1, q2.y, a2); a2 = fmaf(w2, q2.z, a2); a2 = fmaf(w3, q2.w, a2);
        a3 = fmaf(w0, q3.x, a3); a3 = fmaf(w1, q3.y, a3); a3 = fmaf(w2, q3.z, a3); a3 = fmaf(w3, q3.w, a3);
    }

    // pack (j, j+1) pairs into f16x2 via partner shuffle; even j stores
    const float p0 = __shfl_xor_sync(0xffffffffu, a0, 1);
    const float p1 = __shfl_xor_sync(0xffffffffu, a1, 1);
    const float p2 = __shfl_xor_sync(0xffffffffu, a2, 1);
    const float p3 = __shfl_xor_sync(0xffffffffu, a3, 1);
    if ((j & 1) == 0) {
        const int col = j >> 1;   // 0..31
        half2 h0 = __floats2half2_rn(a0, p0);
        half2 h1 = __floats2half2_rn(a1, p1);
        half2 h2v = __floats2half2_rn(a2, p2);
        half2 h3 = __floats2half2_rn(a3, p3);
        g_zch[(b0 + bg * 4 + 0) * 32 + col] = h2u(h0);
        g_zch[(b0 + bg * 4 + 1) * 32 + col] = h2u(h1);
        g_zch[(b0 + bg * 4 + 2) * 32 + col] = h2u(h2v);
        g_zch[(b0 + bg * 4 + 3) * 32 + col] = h2u(h3);
    }

    if (tid < 32) {
        const int bl = tid >> 1;
        const int isn = tid & 1;
        const float* wv = isn ? Wn : Wb;
        const float* zz = sz + bl * LATENT;
        float acc = isn ? bnv[0] : bbv[0];
        #pragma unroll 8
        for (int k = 0; k < LATENT; k++) acc = fmaf(wv[k], zz[k], acc);
        float sp = fmaxf(acc, 0.0f) + log1pf(expf(-fabsf(acc)));
        if (isn) g_ndt[b0 + bl] = sp + 0.05f;
        else     g_halfb[b0 + bl] = 0.5f * (sp + 0.3f);
    }
}

// ---------------------------------------------------------------------------
// Main SDE kernel. Lane pair (2q, 2q+1) serves two sims of one b; each lane
// owns 32 of 64 hidden units (16 f16x2 pairs, ALL weights in registers) and
// evaluates BOTH sims' hidden layers (shared base HFMA2), but owns the tail
// and survival state of only ONE sim (even lane -> sim A = q&7, odd lane ->
// sim B = (q&7)+8). x is exchanged as packed f16 at iteration start (1 SHFL
// + 2 SEL); dot reduction via packed-f16 exchange + HADD2; h2sum only for
// my sim. 64-thread blocks (9/SM cap) for finer wave granularity: waves
// 3.46 -> 3.08 and warps/SM 16 -> 18. Block 64 = 2 warps = 4 b's.
// ---------------------------------------------------------------------------
__global__ __launch_bounds__(64, 9) void sde_kernel(
    const float* __restrict__ W1, const float* __restrict__ W2,
    const float* __restrict__ b2, const float* __restrict__ noise,
    const float* __restrict__ osc, const float* __restrict__ obi,
    float* __restrict__ out)
{
    const int tid  = threadIdx.x;
    const int lane = tid & 31;
    const int wrp  = tid >> 5;        // warp 0..1
    const int q    = lane >> 1;       // pair 0..15
    const int half = lane & 1;        // unit-half AND tail-parity
    const int b    = blockIdx.x * 4 + wrp * 2 + (q >> 3);
    const int jbase = half * 32;

    // weights: 16 f16x2 pairs each = 80 u32 regs
    half2 w1x2[16], w1t2[16], zc2[16], w2a2[16], w2b2[16];
    #pragma unroll
    for (int p = 0; p < 16; p++) {
        const int j = jbase + p * 2;
        w1x2[p] = __floats2half2_rn(W1[j * 130],     W1[(j + 1) * 130]);
        w1t2[p] = __floats2half2_rn(W1[j * 130 + 1], W1[(j + 1) * 130 + 1]);
        zc2[p]  = u2h(g_zch[b * 32 + half * 16 + p]);
        w2a2[p] = __floats2half2_rn(W2[j],       W2[j + 1]);
        w2b2[p] = __floats2half2_rn(W2[HID + j], W2[HID + j + 1]);
    }
    const float b2x = b2[0], b2y = b2[1];
    const float half_b = g_halfb[b];
    const half2 hzero = __floats2half2_rn(0.0f, 0.0f);

    // my sim: even lane -> sA = q&7; odd lane -> sA+8
    const int nidx = b * SS + (q & 7) + half * 8;
    float x_my = 0.0f, p_my = 1.0f, rt_my = 0.0f, cr_my = 0.0f;
    float nz_my = noise[nidx];

    #pragma unroll 1
    for (int k = 0; k < NSTEPS; k++) {
        const int k1 = (k + 1 < NSTEPS) ? (k + 1) : (NSTEPS - 1);
        const float nz_next = noise[k1 * (BB * SS) + nidx];
        const float tk = (float)k * DTC;
        const half2 tkh = __float2half2_rn(tk);

        // exchange x's in packed f16 (both halves carry my x)
        const unsigned xs = h2u(__float2half2_rn(x_my));
        const unsigned xr = __shfl_xor_sync(0xffffffffu, xs, 1);
        const half2 xhA = u2h(half ? xr : xs);
        const half2 xhB = u2h(half ? xs : xr);

        half2 daA = hzero, dbA = hzero, daB = hzero, dbB = hzero;
        #pragma unroll
        for (int p = 0; p < 16; p++) {
            const half2 base = __hfma2(tkh, w1t2[p], zc2[p]);   // shared A/B
            const half2 uA = __hfma2(xhA, w1x2[p], base);
            const half2 uB = __hfma2(xhB, w1x2[p], base);
            const half2 hA = tanh2h(uA);
            const half2 hB = tanh2h(uB);
            daA = __hfma2(hA, w2a2[p], daA);
            dbA = __hfma2(hA, w2b2[p], dbA);
            daB = __hfma2(hB, w2a2[p], daB);
            dbB = __hfma2(hB, w2b2[p], dbB);
        }
        // packed-f16 exchange: even sends its B-partials, odd its A-partials
        const unsigned da_send = half ? h2u(daA) : h2u(daB);
        const unsigned db_send = half ? h2u(dbA) : h2u(dbB);
        const unsigned da_recv = __shfl_xor_sync(0xffffffffu, da_send, 1);
        const unsigned db_recv = __shfl_xor_sync(0xffffffffu, db_send, 1);
        const half2 myda = __hadd2(half ? daB : daA, u2h(da_recv));
        const half2 mydb = __hadd2(half ? dbB : dbA, u2h(db_recv));
        const float pd = h2sum(myda);
        const float pf = h2sum(mydb);

        // --- tail for MY sim only ---
        const float dyn0 = pd + b2x;
        const float dyn1 = pf + b2y;
        const float drift = fminf(fmaxf(dyn0, -5.0f), 5.0f);
        const float e1 = ex2f(-fabsf(dyn1) * LOG2E);
        const float spv = fmaxf(dyn1, 0.0f) + lg2f(1.0f + e1) * LN2;
        const float diff = spv + 0.1f;
        x_my = fmaf(diff * SQRT_DT, nz_my, fmaf(drift, DTC, x_my));
        x_my = fminf(fmaxf(x_my, -10.0f), 10.0f);
        const float dist = fabsf(x_my) - half_b;
        const float sg = fmaf(0.5f, tanhapx(10.0f * dist), 0.5f);
        const float hz = fminf(fmaxf(sg, 0.0f), 0.99f);
        const float sb = fmaxf(p_my, EXPM50);
        const float cp = sb * hz;
        p_my = p_my * (1.0f - hz);
        rt_my = fmaf(cp, tk + DTC, rt_my);
        cr_my += (x_my > 0.0f) ? cp : 0.0f;

        nz_my = nz_next;
    }

    const float rem = fmaxf(p_my, EXPM50);
    rt_my = fmaf(rem, (float)NSTEPS * DTC, rt_my);
    cr_my = fmaf(rem, 0.5f, cr_my);
    const float rtms = (rt_my + g_ndt[b]) * 1000.0f;

    // stats per b: each of the 16 lanes of a b-group owns exactly one sim
    float srt = rtms;
    float scr = cr_my;
    #pragma unroll
    for (int off = 1; off < 16; off <<= 1) {
        srt += __shfl_xor_sync(0xffffffffu, srt, off);
        scr += __shfl_xor_sync(0xffffffffu, scr, off);
    }
    const float m = srt * (1.0f / 16.0f);
    const float c = scr * (1.0f / 16.0f);
    const float d = rtms - m;
    float v = d * d;
    #pragma unroll
    for (int off = 1; off < 16; off <<= 1) {
        v += __shfl_xor_sync(0xffffffffu, v, off);
    }

    if ((lane & 15) == 0) {
        const float sd = sqrtf(v * (1.0f / 15.0f));  // ddof=1
        const float o0 = m * osc[0] + obi[0];
        const float o1 = (sd + 0.001f) * osc[1] + obi[1];
        const float o2 = c * osc[2] + obi[2];
        out[b * 3 + 0] = fix_out(o0);
        out[b * 3 + 1] = fix_out(o1);
        out[b * 3 + 2] = fix_out(o2);
    }
}

extern "C" void kernel_launch(void* const* d_in, const int* in_sizes, int n_in,
                              void* d_out, int out_size)
{
    const float* z   = (const float*)d_in[0];
    const float* W1  = (const float*)d_in[1];
    const float* b1  = (const float*)d_in[2];
    const float* W2  = (const float*)d_in[3];
    const float* b2  = (const float*)d_in[4];
    const float* Wb  = (const float*)d_in[5];
    const float* bbv = (const float*)d_in[6];
    const float* Wn  = (const float*)d_in[7];
    const float* bnv = (const float*)d_in[8];
    const float* osc = (const float*)d_in[9];
    const float* obi = (const float*)d_in[10];
    const float* noise = (const float*)d_in[11];
    float* out = (float*)d_out;

    precompute_kernel<<<BB / 16, 256>>>(z, W1, b1, Wb, bbv, Wn, bnv);
    sde_kernel<<<BB / 4, 64>>>(W1, W2, b2, noise, osc, obi, out);
}